// round 9
// baseline (speedup 1.0000x reference)
#include <cuda_runtime.h>
#include <float.h>
#include <math.h>

#define MAXROWS 8192
#define D32     32000
#define NF4     (D32 / 4)      // 8000
#define NT1     512
#define NW1     (NT1 / 32)
#define KFULL   15             // 8000 = 15*512 + 320
#define REM     320
#define NT2     256
#define RPB     8              // row-warps per K2 block
#define CAP     24             // per-lane candidate floats

__device__ float    g_rowmax[MAXROWS];
__device__ unsigned g_mask[MAXROWS * NT1];
__device__ float    g_rowloss[MAXROWS];

#define M4(v) fmaxf(fmaxf((v).x, (v).y), fmaxf((v).z, (v).w))

__device__ __forceinline__ float warpMax(float v) {
#pragma unroll
    for (int o = 16; o; o >>= 1) v = fmaxf(v, __shfl_xor_sync(0xffffffffu, v, o));
    return v;
}
// Warp sum, identical value broadcast to all lanes (lane 0's order -> uniform).
__device__ __forceinline__ float warpSumB(float v) {
#pragma unroll
    for (int o = 16; o; o >>= 1) v += __shfl_xor_sync(0xffffffffu, v, o);
    return __shfl_sync(0xffffffffu, v, 0);
}
__device__ __forceinline__ float warpSumDown(float v) {
#pragma unroll
    for (int o = 16; o; o >>= 1) v += __shfl_down_sync(0xffffffffu, v, o);
    return v;   // valid in lane 0
}

// Robust target load: auto-detect int32 vs int64 storage (int64 -> odd words zero).
__device__ __forceinline__ int load_target(const void* tgt, int row, int n, int d) {
    const int* t32 = (const int*)tgt;
    int lim = (n < 32) ? n : 32;
    bool is64 = true;
    for (int i = 0; i < lim; i++) is64 = is64 && (t32[2 * i + 1] == 0);
    long long v = is64 ? ((const long long*)tgt)[row] : (long long)t32[row];
    int t = (int)v;
    if (t < 0 || t >= d) t = 0;
    return t;
}

// ============ K1 (d==32000): pure rowmax stream + exact-threshold bits ============
__global__ __launch_bounds__(NT1, 2) void filter32k(const float* __restrict__ in) {
    int row = blockIdx.x, tid = threadIdx.x;
    int lane = tid & 31, warp = tid >> 5;
    const float4* p4 = (const float4*)(in + (size_t)row * D32);
    __shared__ float swm[NW1];

    float m4[KFULL + 1];
#pragma unroll
    for (int k = 0; k < KFULL; k++) {
        float4 v = p4[k * NT1 + tid];
        m4[k] = M4(v);
    }
    if (tid < REM) {
        float4 v = p4[KFULL * NT1 + tid];
        m4[KFULL] = M4(v);
    } else m4[KFULL] = -FLT_MAX;

    float rm = m4[0];
#pragma unroll
    for (int k = 1; k <= KFULL; k++) rm = fmaxf(rm, m4[k]);

    float wv = warpMax(rm);
    if (lane == 0) swm[warp] = wv;
    __syncthreads();
    float bmax = swm[0];
#pragma unroll
    for (int w = 1; w < NW1; w++) bmax = fmaxf(bmax, swm[w]);

    float th = bmax - 1.503f;            // raw units; kept covers X > maxX - 0.7515
    unsigned hit = 0;
#pragma unroll
    for (int k = 0; k <= KFULL; k++)
        if (m4[k] > th) hit |= (1u << k);

    g_mask[row * NT1 + tid] = hit;
    if (tid == 0) g_rowmax[row] = bmax;
}

// ============ K2 (d==32000): warp-per-row gather + bisection, no barriers ============
__device__ __forceinline__ float warp_relu2(const float* xr, float tau) {
    float s = 0.f;
    int lane = threadIdx.x & 31;
    for (int i = lane; i < D32; i += 32) {
        float t = fmaxf(fmaf(0.5f, __ldg(xr + i), -tau), 0.f);
        s = fmaf(t, t, s);
    }
    return warpSumB(s);
}

__global__ __launch_bounds__(NT2) void bisect32k(const float* __restrict__ in,
                                                 const void* __restrict__ tgt, int n) {
    int lane = threadIdx.x & 31, w = threadIdx.x >> 5;
    int row = blockIdx.x * RPB + w;
    __shared__ float scand[RPB][CAP][32];     // 24.6 KB
    if (row >= n) return;                     // warp-autonomous; no barriers in kernel

    const float* xr = in + (size_t)row * D32;
    const float4* p4 = (const float4*)xr;

    float bmax    = g_rowmax[row];
    float maxX    = 0.5f * bmax;
    float thr     = bmax - 1.503f;            // raw; same compare as K1
    float tau_lo0 = maxX - 1.0f;
    float tau_hi0 = maxX - 0.00559017f;       // (1/32000)^0.5
    float guard   = maxX - 0.75145f;          // min legal tau_m is maxX-0.75140

    // ---- gather: per-lane columns, exact per-element threshold, store X ----
    int cnt = 0;
#pragma unroll 1
    for (int t = 0; t < 16; t++) {
        int c = lane + 32 * t;
        unsigned hm = g_mask[row * NT1 + c];
        while (hm) {
            int b = __ffs(hm) - 1;
            hm &= hm - 1;
            float4 v = p4[b * NT1 + c];
            if (v.x > thr) { if (cnt < CAP) scand[w][cnt][lane] = 0.5f * v.x; cnt++; }
            if (v.y > thr) { if (cnt < CAP) scand[w][cnt][lane] = 0.5f * v.y; cnt++; }
            if (v.z > thr) { if (cnt < CAP) scand[w][cnt][lane] = 0.5f * v.z; cnt++; }
            if (v.w > thr) { if (cnt < CAP) scand[w][cnt][lane] = 0.5f * v.w; cnt++; }
        }
    }
    bool slow = __any_sync(0xffffffffu, cnt > CAP);
    int  myc  = slow ? 0 : cnt;

    // ---- 15 bisection iterations, warp-local ----
    float tau_lo = tau_lo0;
    float dm     = tau_hi0 - tau_lo0;
    float tau_m  = tau_lo0;
    int   gtrip  = 0;
#pragma unroll 1
    for (int it = 0; it < 15; it++) {
        dm *= 0.5f;
        tau_m = tau_lo + dm;
        if (tau_m < guard) gtrip = 1;         // uniform (tau_m uniform)
        float s = 0.f;
        for (int j = 0; j < myc; j++) {
            float t = fmaxf(scand[w][j][lane] - tau_m, 0.f);
            s = fmaf(t, t, s);
        }
        s = warpSumB(s);
        tau_lo = (s - 1.0f >= 0.f) ? tau_m : tau_lo;
    }

    float S3, PX, tau_f;
    if (!slow && !gtrip) {
        tau_f = tau_m;
        float s3 = 0.f, px = 0.f;
        for (int j = 0; j < myc; j++) {
            float X = scand[w][j][lane];
            float t = fmaxf(X - tau_f, 0.f);
            float p = t * t;
            s3 = fmaf(p, t, s3);
            px = fmaf(p, X, px);
        }
        S3 = warpSumDown(s3);
        PX = warpSumDown(px);
    } else {
        // ---- warp-local full-reference slow path (rare) ----
        float tl = tau_lo0;
        float f_lo = warp_relu2(xr, tl) - 1.0f;
        float dm2 = tau_hi0 - tl, tm = tl;
#pragma unroll 1
        for (int it = 0; it < 15; it++) {
            dm2 *= 0.5f;
            tm = tl + dm2;
            float fm = warp_relu2(xr, tm) - 1.0f;
            tl = (fm * f_lo >= 0.f) ? tm : tl;
        }
        tau_f = tm;
        float s3 = 0.f, px = 0.f;
        for (int i = lane; i < D32; i += 32) {
            float X = 0.5f * __ldg(xr + i);
            float t = fmaxf(X - tau_f, 0.f);
            float p = t * t;
            s3 = fmaf(p, t, s3);
            px = fmaf(p, X, px);
        }
        S3 = warpSumDown(s3);
        PX = warpSumDown(px);
    }

    if (lane == 0) {
        int t = load_target(tgt, row, n, D32);
        float xt = __ldg(xr + t);
        // loss = (1-S3)/(alpha*(alpha-1)) + sum(p*input) - input[target]
        //      = (1-S3)/0.75 + 2*PX - xt          (input = 2*X)
        g_rowloss[row] = (1.0f - S3) / 0.75f + 2.0f * PX - xt;
    }
}

// ============ Generic fallback pipeline (any d; correctness only) ============
__device__ __forceinline__ float blockSumAllG(float v, float* sbuf) {
    int lane = threadIdx.x & 31, warp = threadIdx.x >> 5;
#pragma unroll
    for (int o = 16; o; o >>= 1) v += __shfl_xor_sync(0xffffffffu, v, o);
    __syncthreads();
    if (lane == 0) sbuf[warp] = v;
    __syncthreads();
    float s = 0.f;
#pragma unroll
    for (int w2 = 0; w2 < 8; w2++) s += sbuf[w2];
    return s;
}
__global__ __launch_bounds__(256) void rowmax_gen(const float* __restrict__ in, int d) {
    int row = blockIdx.x;
    const float* xr = in + (size_t)row * d;
    __shared__ float sb[8];
    float m = -FLT_MAX;
    for (int i = threadIdx.x; i < d; i += 256) m = fmaxf(m, xr[i]);
    m = warpMax(m);
    if ((threadIdx.x & 31) == 0) sb[threadIdx.x >> 5] = m;
    __syncthreads();
    if (threadIdx.x == 0) {
        float b = sb[0];
        for (int w2 = 1; w2 < 8; w2++) b = fmaxf(b, sb[w2]);
        g_rowmax[row] = b;
    }
}
__global__ __launch_bounds__(256) void bisect_gen(const float* __restrict__ in,
                                                  const void* __restrict__ tgt,
                                                  int d, int n) {
    int row = blockIdx.x;
    const float* xr = in + (size_t)row * d;
    __shared__ float sb[8];
    float maxX = 0.5f * g_rowmax[row];
    float tl = maxX - 1.0f;
    float th0 = maxX - (float)(1.0 / sqrt((double)d));
    float s = 0.f;
    for (int i = threadIdx.x; i < d; i += 256) {
        float t = fmaxf(fmaf(0.5f, __ldg(xr + i), -tl), 0.f);
        s = fmaf(t, t, s);
    }
    float f_lo = blockSumAllG(s, sb) - 1.0f;
    float dm = th0 - tl, tm = tl;
#pragma unroll 1
    for (int it = 0; it < 15; it++) {
        dm *= 0.5f;
        tm = tl + dm;
        float q = 0.f;
        for (int i = threadIdx.x; i < d; i += 256) {
            float t = fmaxf(fmaf(0.5f, __ldg(xr + i), -tm), 0.f);
            q = fmaf(t, t, q);
        }
        float fm = blockSumAllG(q, sb) - 1.0f;
        tl = (fm * f_lo >= 0.f) ? tm : tl;
    }
    float s3 = 0.f, px = 0.f;
    for (int i = threadIdx.x; i < d; i += 256) {
        float X = 0.5f * __ldg(xr + i);
        float t = fmaxf(X - tm, 0.f);
        float p = t * t;
        s3 = fmaf(p, t, s3);
        px = fmaf(p, X, px);
    }
    float S3 = blockSumAllG(s3, sb);
    float PX = blockSumAllG(px, sb);
    if (threadIdx.x == 0) {
        int t = load_target(tgt, row, n, d);
        g_rowloss[row] = (1.0f - S3) / 0.75f + 2.0f * PX - __ldg(xr + t);
    }
}

// ============ K3: deterministic mean over rows ============
__global__ __launch_bounds__(1024) void reduce_kernel(float* __restrict__ out, int n) {
    __shared__ float sbuf[32];
    float s = 0.f;
    for (int i = threadIdx.x; i < n; i += 1024) s += g_rowloss[i];
#pragma unroll
    for (int o = 16; o; o >>= 1) s += __shfl_down_sync(0xffffffffu, s, o);
    if ((threadIdx.x & 31) == 0) sbuf[threadIdx.x >> 5] = s;
    __syncthreads();
    if (threadIdx.x < 32) {
        float x = sbuf[threadIdx.x];
#pragma unroll
        for (int o = 16; o; o >>= 1) x += __shfl_down_sync(0xffffffffu, x, o);
        if (threadIdx.x == 0) out[0] = x / (float)n;
    }
}

extern "C" void kernel_launch(void* const* d_in, const int* in_sizes, int n_in,
                              void* d_out, int out_size) {
    // Pick logits vs targets by size: the big buffer is the [n, d] logits.
    int idx_in = 0, idx_tg = 1;
    if (n_in >= 2 && in_sizes[1] > in_sizes[0]) { idx_in = 1; idx_tg = 0; }
    const float* in  = (const float*)d_in[idx_in];
    const void*  tgt = d_in[idx_tg];

    int n = in_sizes[idx_tg];
    if (n <= 0) n = 1;
    int d = in_sizes[idx_in] / n;
    if (n > MAXROWS) n = MAXROWS;

    if (d == D32) {
        filter32k<<<n, NT1>>>(in);
        bisect32k<<<(n + RPB - 1) / RPB, NT2>>>(in, tgt, n);
    } else {
        rowmax_gen<<<n, 256>>>(in, d);
        bisect_gen<<<n, 256>>>(in, tgt, d, n);
    }
    reduce_kernel<<<1, 1024>>>((float*)d_out, n);
}

// round 10
// speedup vs baseline: 2.1135x; 2.1135x over previous
#include <cuda_runtime.h>
#include <float.h>
#include <math.h>

#define MAXROWS 8192
#define D32     32000
#define NF4     8000
#define NT      256
#define NW      (NT / 32)
#define CAP     12

__device__ float g_rowloss[MAXROWS];

#define M4(v) fmaxf(fmaxf((v).x, (v).y), fmaxf((v).z, (v).w))

__device__ __forceinline__ float warpMax(float v) {
#pragma unroll
    for (int o = 16; o; o >>= 1) v = fmaxf(v, __shfl_xor_sync(0xffffffffu, v, o));
    return v;
}
__device__ __forceinline__ float warpSumB(float v) {   // uniform across the warp
#pragma unroll
    for (int o = 16; o; o >>= 1) v += __shfl_xor_sync(0xffffffffu, v, o);
    return __shfl_sync(0xffffffffu, v, 0);
}
// Block sum to all threads (fixed order -> deterministic); 2 barriers.
__device__ __forceinline__ float blockSumAll(float v, float* sbuf) {
    int lane = threadIdx.x & 31, warp = threadIdx.x >> 5;
#pragma unroll
    for (int o = 16; o; o >>= 1) v += __shfl_xor_sync(0xffffffffu, v, o);
    __syncthreads();
    if (lane == 0) sbuf[warp] = v;
    __syncthreads();
    float s = 0.f;
#pragma unroll
    for (int w = 0; w < NW; w++) s += sbuf[w];
    return s;
}

// Robust target load: auto-detect int32 vs int64 storage (int64 -> odd words zero).
__device__ __forceinline__ int load_target(const void* tgt, int row, int n, int d) {
    const int* t32 = (const int*)tgt;
    int lim = (n < 32) ? n : 32;
    bool is64 = true;
    for (int i = 0; i < lim; i++) is64 = is64 && (t32[2 * i + 1] == 0);
    long long v = is64 ? ((const long long*)tgt)[row] : (long long)t32[row];
    int t = (int)v;
    if (t < 0 || t >= d) t = 0;
    return t;
}

// ======================= fused kernel for d == 32000 =======================
__global__ __launch_bounds__(NT, 4) void tsallis32k(const float* __restrict__ in,
                                                    const void* __restrict__ tgt, int n) {
    int row  = blockIdx.x;
    int tid  = threadIdx.x;
    int lane = tid & 31, warp = tid >> 5;
    const float4* p4 = (const float4*)(in + (size_t)row * D32);
    const float*  xr = in + (size_t)row * D32;

    __shared__ float4 cand[CAP][NT];     // 48 KB, slot-major (conflict-free)
    __shared__ int    scnt[NT];
    __shared__ float  swm[NW];
    __shared__ float  sred[NW];
    __shared__ int    s_slow;

    if (tid == 0) s_slow = 0;
    __syncthreads();

    float rm = -FLT_MAX;   // running max, raw units
    int   cnt = 0;

    // ---- warm-up: rounds 0..7, keep only per-f4 maxes in registers ----
    float m4a[8];
#pragma unroll
    for (int u = 0; u < 8; u++) {
        float4 v = p4[u * NT + tid];
        m4a[u] = M4(v);
    }
    rm = fmaxf(fmaxf(fmaxf(m4a[0], m4a[1]), fmaxf(m4a[2], m4a[3])),
               fmaxf(fmaxf(m4a[4], m4a[5]), fmaxf(m4a[6], m4a[7])));
    {
        float wv = warpMax(rm);
        if (lane == 0) swm[warp] = wv;
        __syncthreads();
    }
    float bm = swm[0];
#pragma unroll
    for (int w = 1; w < NW; w++) bm = fmaxf(bm, swm[w]);
    float th = bm - 1.76f;               // raw; kept covers X > maxX - 0.88
    __syncthreads();                     // swm reused below

    // warm-up stores: reload hit f4s from (warm) L2
#pragma unroll
    for (int u = 0; u < 8; u++) {
        if (m4a[u] > th) {
            float4 v = p4[u * NT + tid];
            if (cnt < CAP) cand[cnt][tid] = v;
            cnt++;
        }
    }

    // ---- steady stream: groups of 8 unconditional loads + predicated stores ----
#pragma unroll 1
    for (int g = 0; g < 2; g++) {
        int k0 = 8 + g * 8;              // rounds 8..15, 16..23
        float4 v[8];
#pragma unroll
        for (int u = 0; u < 8; u++) v[u] = p4[(k0 + u) * NT + tid];
        float m4[8];
#pragma unroll
        for (int u = 0; u < 8; u++) m4[u] = M4(v[u]);
#pragma unroll
        for (int u = 0; u < 8; u++) {
            if (m4[u] > th) {
                if (cnt < CAP) cand[cnt][tid] = v[u];
                cnt++;
            }
        }
        float gm = fmaxf(fmaxf(fmaxf(m4[0], m4[1]), fmaxf(m4[2], m4[3])),
                         fmaxf(fmaxf(m4[4], m4[5]), fmaxf(m4[6], m4[7])));
        rm = fmaxf(rm, gm);
        // block refresh of th (tightens; still <= rawmax-1.76 -> superset-safe)
        float wv = warpMax(rm);
        __syncthreads();
        if (lane == 0) swm[warp] = wv;
        __syncthreads();
        float b2 = swm[0];
#pragma unroll
        for (int w = 1; w < NW; w++) b2 = fmaxf(b2, swm[w]);
        th = fmaxf(th, b2 - 1.76f);
    }
    {   // rounds 24..30 (7 rounds)
        float4 v[7];
#pragma unroll
        for (int u = 0; u < 7; u++) v[u] = p4[(24 + u) * NT + tid];
        float m4[7];
#pragma unroll
        for (int u = 0; u < 7; u++) m4[u] = M4(v[u]);
#pragma unroll
        for (int u = 0; u < 7; u++) {
            if (m4[u] > th) {
                if (cnt < CAP) cand[cnt][tid] = v[u];
                cnt++;
            }
        }
        float gm = m4[0];
#pragma unroll
        for (int u = 1; u < 7; u++) gm = fmaxf(gm, m4[u]);
        rm = fmaxf(rm, gm);
    }
    // remainder: f4 indices 7936..7999 (tid < 64)
    if (tid < 64) {
        float4 v = p4[31 * NT + tid];
        float m = M4(v);
        rm = fmaxf(rm, m);
        if (m > th) {
            if (cnt < CAP) cand[cnt][tid] = v;
            cnt++;
        }
    }

    if (cnt > CAP) atomicOr(&s_slow, 1);
    scnt[tid] = (cnt < CAP) ? cnt : CAP;

    // ---- final block max; barrier b1 makes cand/scnt/flags visible ----
    {
        float wv = warpMax(rm);
        __syncthreads();
        if (lane == 0) swm[warp] = wv;
        __syncthreads();                          // b1
    }
    float bmax = swm[0];
#pragma unroll
    for (int w = 1; w < NW; w++) bmax = fmaxf(bmax, swm[w]);

    float maxX    = 0.5f * bmax;
    float tau_lo0 = maxX - 1.0f;
    float tau_hi0 = maxX - 0.00559017f;           // (1/32000)^0.5
    float guard   = maxX - 0.8790f;               // ladder value 0.87570 stays legal

    bool fastok = (s_slow == 0);

    float S3 = 0.f, PX = 0.f;
    // ---- warp-0 tail: 15 bisection rounds + finals, no barriers ----
    if (warp == 0 && fastok) {
        float tau_lo = tau_lo0;
        float dm     = tau_hi0 - tau_lo0;
        float tau_m  = tau_lo0;
        int   gtrip  = 0;
#pragma unroll 1
        for (int it = 0; it < 15; it++) {
            dm *= 0.5f;
            tau_m = tau_lo + dm;
            if (tau_m < guard) gtrip = 1;
            float s = 0.f;
#pragma unroll 1
            for (int g = 0; g < 8; g++) {
                int t = lane + 32 * g;
                int c = scnt[t];
                for (int j = 0; j < c; j++) {
                    float4 v = cand[j][t];
                    float q;
                    q = fmaxf(fmaf(0.5f, v.x, -tau_m), 0.f); s = fmaf(q, q, s);
                    q = fmaxf(fmaf(0.5f, v.y, -tau_m), 0.f); s = fmaf(q, q, s);
                    q = fmaxf(fmaf(0.5f, v.z, -tau_m), 0.f); s = fmaf(q, q, s);
                    q = fmaxf(fmaf(0.5f, v.w, -tau_m), 0.f); s = fmaf(q, q, s);
                }
            }
            s = warpSumB(s);
            tau_lo = (s - 1.0f >= 0.f) ? tau_m : tau_lo;   // f_lo >= 0 always
        }
        if (gtrip) {
            if (lane == 0) s_slow = 1;
        } else {
            float s3 = 0.f, px = 0.f;
#pragma unroll 1
            for (int g = 0; g < 8; g++) {
                int t = lane + 32 * g;
                int c = scnt[t];
                for (int j = 0; j < c; j++) {
                    float4 v = cand[j][t];
                    float X, q, p;
                    X = 0.5f * v.x; q = fmaxf(X - tau_m, 0.f); p = q * q; s3 = fmaf(p, q, s3); px = fmaf(p, X, px);
                    X = 0.5f * v.y; q = fmaxf(X - tau_m, 0.f); p = q * q; s3 = fmaf(p, q, s3); px = fmaf(p, X, px);
                    X = 0.5f * v.z; q = fmaxf(X - tau_m, 0.f); p = q * q; s3 = fmaf(p, q, s3); px = fmaf(p, X, px);
                    X = 0.5f * v.w; q = fmaxf(X - tau_m, 0.f); p = q * q; s3 = fmaf(p, q, s3); px = fmaf(p, X, px);
                }
            }
            S3 = warpSumB(s3);
            PX = warpSumB(px);
        }
    }
    __syncthreads();                              // b2

    if (s_slow) {
        // ---- block-parallel full-reference slow path (rare rows) ----
        float tl = tau_lo0;
        float s = 0.f;
        for (int i = tid; i < D32; i += NT) {
            float q = fmaxf(fmaf(0.5f, __ldg(xr + i), -tl), 0.f);
            s = fmaf(q, q, s);
        }
        float f_lo = blockSumAll(s, sred) - 1.0f;
        float dm2 = tau_hi0 - tl, tm = tl;
#pragma unroll 1
        for (int it = 0; it < 15; it++) {
            dm2 *= 0.5f;
            tm = tl + dm2;
            float q2 = 0.f;
            for (int i = tid; i < D32; i += NT) {
                float q = fmaxf(fmaf(0.5f, __ldg(xr + i), -tm), 0.f);
                q2 = fmaf(q, q, q2);
            }
            float fm = blockSumAll(q2, sred) - 1.0f;
            tl = (fm * f_lo >= 0.f) ? tm : tl;
        }
        float s3 = 0.f, px = 0.f;
        for (int i = tid; i < D32; i += NT) {
            float X = 0.5f * __ldg(xr + i);
            float q = fmaxf(X - tm, 0.f);
            float p = q * q;
            s3 = fmaf(p, q, s3);
            px = fmaf(p, X, px);
        }
        float S3b = blockSumAll(s3, sred);
        float PXb = blockSumAll(px, sred);
        if (tid == 0) {
            int t = load_target(tgt, row, n, D32);
            g_rowloss[row] = (1.0f - S3b) / 0.75f + 2.0f * PXb - __ldg(xr + t);
        }
    } else if (warp == 0 && lane == 0) {
        int t = load_target(tgt, row, n, D32);
        float xt = __ldg(xr + t);
        // loss = (1-S3)/(alpha*(alpha-1)) + sum(p*input) - input[target]
        //      = (1-S3)/0.75 + 2*PX - xt          (input = 2*X)
        g_rowloss[row] = (1.0f - S3) / 0.75f + 2.0f * PX - xt;
    }
}

// ======================= generic fallback (any d) =======================
__global__ __launch_bounds__(NT) void tsallis_gen(const float* __restrict__ in,
                                                  const void* __restrict__ tgt,
                                                  int d, int n) {
    int row = blockIdx.x;
    const float* xr = in + (size_t)row * d;
    __shared__ float sred[NW];
    float m = -FLT_MAX;
    for (int i = threadIdx.x; i < d; i += NT) m = fmaxf(m, xr[i]);
    m = warpMax(m);
    __syncthreads();
    if ((threadIdx.x & 31) == 0) sred[threadIdx.x >> 5] = m;
    __syncthreads();
    float bmax = sred[0];
#pragma unroll
    for (int w = 1; w < NW; w++) bmax = fmaxf(bmax, sred[w]);
    float maxX = 0.5f * bmax;
    float tl = maxX - 1.0f;
    float th0 = maxX - (float)(1.0 / sqrt((double)d));
    float s = 0.f;
    for (int i = threadIdx.x; i < d; i += NT) {
        float q = fmaxf(fmaf(0.5f, __ldg(xr + i), -tl), 0.f);
        s = fmaf(q, q, s);
    }
    float f_lo = blockSumAll(s, sred) - 1.0f;
    float dm = th0 - tl, tm = tl;
#pragma unroll 1
    for (int it = 0; it < 15; it++) {
        dm *= 0.5f;
        tm = tl + dm;
        float q2 = 0.f;
        for (int i = threadIdx.x; i < d; i += NT) {
            float q = fmaxf(fmaf(0.5f, __ldg(xr + i), -tm), 0.f);
            q2 = fmaf(q, q, q2);
        }
        float fm = blockSumAll(q2, sred) - 1.0f;
        tl = (fm * f_lo >= 0.f) ? tm : tl;
    }
    float s3 = 0.f, px = 0.f;
    for (int i = threadIdx.x; i < d; i += NT) {
        float X = 0.5f * __ldg(xr + i);
        float q = fmaxf(X - tm, 0.f);
        float p = q * q;
        s3 = fmaf(p, q, s3);
        px = fmaf(p, X, px);
    }
    float S3 = blockSumAll(s3, sred);
    float PX = blockSumAll(px, sred);
    if (threadIdx.x == 0) {
        int t = load_target(tgt, row, n, d);
        g_rowloss[row] = (1.0f - S3) / 0.75f + 2.0f * PX - __ldg(xr + t);
    }
}

// ======================= mean over rows =======================
__global__ __launch_bounds__(1024) void reduce_kernel(float* __restrict__ out, int n) {
    __shared__ float sbuf[32];
    float s = 0.f;
    for (int i = threadIdx.x; i < n; i += 1024) s += g_rowloss[i];
#pragma unroll
    for (int o = 16; o; o >>= 1) s += __shfl_down_sync(0xffffffffu, s, o);
    if ((threadIdx.x & 31) == 0) sbuf[threadIdx.x >> 5] = s;
    __syncthreads();
    if (threadIdx.x < 32) {
        float x = sbuf[threadIdx.x];
#pragma unroll
        for (int o = 16; o; o >>= 1) x += __shfl_down_sync(0xffffffffu, x, o);
        if (threadIdx.x == 0) out[0] = x / (float)n;
    }
}

extern "C" void kernel_launch(void* const* d_in, const int* in_sizes, int n_in,
                              void* d_out, int out_size) {
    int idx_in = 0, idx_tg = 1;
    if (n_in >= 2 && in_sizes[1] > in_sizes[0]) { idx_in = 1; idx_tg = 0; }
    const float* in  = (const float*)d_in[idx_in];
    const void*  tgt = d_in[idx_tg];

    int n = in_sizes[idx_tg];
    if (n <= 0) n = 1;
    int d = in_sizes[idx_in] / n;
    if (n > MAXROWS) n = MAXROWS;

    if (d == D32) tsallis32k<<<n, NT>>>(in, tgt, n);
    else          tsallis_gen<<<n, NT>>>(in, tgt, d, n);
    reduce_kernel<<<1, 1024>>>((float*)d_out, n);
}

// round 11
// speedup vs baseline: 2.7767x; 1.3138x over previous
#include <cuda_runtime.h>
#include <float.h>
#include <math.h>

#define MAXROWS 8192
#define D32     32000
#define NT1     512
#define NW1     (NT1 / 32)
#define KFULL   15             // 8000 f4 = 15*512 + 320
#define REM     320
#define NT2     256
#define NW2     (NT2 / 32)
#define CAP     12             // per-thread kept-f4 slots in K2 (48 KB)

__device__ float    g_rowmax[MAXROWS];
__device__ unsigned g_mask[MAXROWS * NT1];
__device__ float    g_rowloss[MAXROWS];

#define M4(v) fmaxf(fmaxf((v).x, (v).y), fmaxf((v).z, (v).w))

__device__ __forceinline__ float warpMax(float v) {
#pragma unroll
    for (int o = 16; o; o >>= 1) v = fmaxf(v, __shfl_xor_sync(0xffffffffu, v, o));
    return v;
}
// Block sum to all threads (fixed order -> deterministic, uniform).
__device__ __forceinline__ float blockSumAll2(float v, float* sbuf) {
    int lane = threadIdx.x & 31, warp = threadIdx.x >> 5;
#pragma unroll
    for (int o = 16; o; o >>= 1) v += __shfl_xor_sync(0xffffffffu, v, o);
    __syncthreads();
    if (lane == 0) sbuf[warp] = v;
    __syncthreads();
    float s = 0.f;
#pragma unroll
    for (int w = 0; w < NW2; w++) s += sbuf[w];
    return s;
}

// Robust target load: auto-detect int32 vs int64 storage (int64 -> odd words zero).
__device__ __forceinline__ int load_target(const void* tgt, int row, int n, int d) {
    const int* t32 = (const int*)tgt;
    int lim = (n < 32) ? n : 32;
    bool is64 = true;
    for (int i = 0; i < lim; i++) is64 = is64 && (t32[2 * i + 1] == 0);
    long long v = is64 ? ((const long long*)tgt)[row] : (long long)t32[row];
    int t = (int)v;
    if (t < 0 || t >= d) t = 0;
    return t;
}

// ============ K1 (d==32000): pure rowmax stream + exact-threshold bits ============
// Measured at 79.7-84.6 us, 84% DRAM. Threshold rowmax-2.0 => kept covers X > maxX-1,
// which is sufficient for EVERY bisection probe (tau_m > maxX-1 always).
__global__ __launch_bounds__(NT1, 2) void filter32k(const float* __restrict__ in) {
    int row = blockIdx.x, tid = threadIdx.x;
    int lane = tid & 31, warp = tid >> 5;
    const float4* p4 = (const float4*)(in + (size_t)row * D32);
    __shared__ float swm[NW1];

    float m4[KFULL + 1];
#pragma unroll
    for (int k = 0; k < KFULL; k++) {
        float4 v = p4[k * NT1 + tid];
        m4[k] = M4(v);
    }
    if (tid < REM) {
        float4 v = p4[KFULL * NT1 + tid];
        m4[KFULL] = M4(v);
    } else m4[KFULL] = -FLT_MAX;

    float rm = m4[0];
#pragma unroll
    for (int k = 1; k <= KFULL; k++) rm = fmaxf(rm, m4[k]);

    float wv = warpMax(rm);
    if (lane == 0) swm[warp] = wv;
    __syncthreads();
    float bmax = swm[0];
#pragma unroll
    for (int w = 1; w < NW1; w++) bmax = fmaxf(bmax, swm[w]);

    float th = bmax - 2.0f;              // raw units: exactly X > maxX - 1
    unsigned hit = 0;
#pragma unroll
    for (int k = 0; k <= KFULL; k++)
        if (m4[k] > th) hit |= (1u << k);

    g_mask[row * NT1 + tid] = hit;
    if (tid == 0) g_rowmax[row] = bmax;
}

// ============ K2 (d==32000): block-per-row gather + bisection ============
__global__ __launch_bounds__(NT2) void bisect32k(const float* __restrict__ in,
                                                 const void* __restrict__ tgt, int n) {
    int row = blockIdx.x, tid = threadIdx.x;
    const float* xr = in + (size_t)row * D32;
    const float4* p4 = (const float4*)xr;

    __shared__ float4 cand[CAP][NT2];    // 48 KB, slot-major
    __shared__ float  sred[NW2];
    __shared__ int    sflag;

    if (tid == 0) sflag = 0;
    __syncthreads();

    float bmax    = g_rowmax[row];
    float maxX    = 0.5f * bmax;
    float tau_lo0 = maxX - 1.0f;
    float tau_hi0 = maxX - 0.00559017f;  // maxX - (1/32000)^0.5

    // ---- gather: 2 mask columns per thread, parallel scattered loads ----
    int cnt = 0;
#pragma unroll
    for (int j = 0; j < 2; j++) {
        int c = tid + NT2 * j;           // K1 column 0..511
        unsigned hm = g_mask[row * NT1 + c];
        while (hm) {
            int b = __ffs(hm) - 1;
            hm &= hm - 1;
            float4 v = p4[b * NT1 + c];
            if (cnt < CAP) cand[cnt][tid] = v;
            cnt++;
        }
    }
    if (cnt > CAP) atomicOr(&sflag, 1);
    __syncthreads();
    bool slow = (sflag != 0);
    if (slow) cnt = 0;

    // ---- f_lo over the candidate set (contains every element > maxX-1) ----
    float fl = 0.f;
    for (int j = 0; j < cnt; j++) {
        float4 v = cand[j][tid];
        float q;
        q = fmaxf(fmaf(0.5f, v.x, -tau_lo0), 0.f); fl = fmaf(q, q, fl);
        q = fmaxf(fmaf(0.5f, v.y, -tau_lo0), 0.f); fl = fmaf(q, q, fl);
        q = fmaxf(fmaf(0.5f, v.z, -tau_lo0), 0.f); fl = fmaf(q, q, fl);
        q = fmaxf(fmaf(0.5f, v.w, -tau_lo0), 0.f); fl = fmaf(q, q, fl);
    }
    float f_lo = blockSumAll2(fl, sred) - 1.0f;

    // ---- 15 bisection iterations over smem candidates ----
    float tau_lo = tau_lo0;
    float dm     = tau_hi0 - tau_lo0;
    float tau_m  = tau_lo0;
#pragma unroll 1
    for (int it = 0; it < 15; it++) {
        dm *= 0.5f;
        tau_m = tau_lo + dm;
        float s = 0.f;
        for (int j = 0; j < cnt; j++) {
            float4 v = cand[j][tid];
            float q;
            q = fmaxf(fmaf(0.5f, v.x, -tau_m), 0.f); s = fmaf(q, q, s);
            q = fmaxf(fmaf(0.5f, v.y, -tau_m), 0.f); s = fmaf(q, q, s);
            q = fmaxf(fmaf(0.5f, v.z, -tau_m), 0.f); s = fmaf(q, q, s);
            q = fmaxf(fmaf(0.5f, v.w, -tau_m), 0.f); s = fmaf(q, q, s);
        }
        float fm = blockSumAll2(s, sred) - 1.0f;
        tau_lo = (fm * f_lo >= 0.f) ? tau_m : tau_lo;    // uniform
    }

    float S3, PX;
    if (!slow) {
        float s3 = 0.f, px = 0.f;
        for (int j = 0; j < cnt; j++) {
            float4 v = cand[j][tid];
            float X, q, p;
            X = 0.5f * v.x; q = fmaxf(X - tau_m, 0.f); p = q * q; s3 = fmaf(p, q, s3); px = fmaf(p, X, px);
            X = 0.5f * v.y; q = fmaxf(X - tau_m, 0.f); p = q * q; s3 = fmaf(p, q, s3); px = fmaf(p, X, px);
            X = 0.5f * v.z; q = fmaxf(X - tau_m, 0.f); p = q * q; s3 = fmaf(p, q, s3); px = fmaf(p, X, px);
            X = 0.5f * v.w; q = fmaxf(X - tau_m, 0.f); p = q * q; s3 = fmaf(p, q, s3); px = fmaf(p, X, px);
        }
        S3 = blockSumAll2(s3, sred);
        PX = blockSumAll2(px, sred);
    } else {
        // ---- block-parallel full-reference slow path (overflow only, ~never) ----
        float tl = tau_lo0;
        float s0 = 0.f;
        for (int i = tid; i < D32; i += NT2) {
            float q = fmaxf(fmaf(0.5f, __ldg(xr + i), -tl), 0.f);
            s0 = fmaf(q, q, s0);
        }
        float flb = blockSumAll2(s0, sred) - 1.0f;
        float dm2 = tau_hi0 - tl, tm = tl;
#pragma unroll 1
        for (int it = 0; it < 15; it++) {
            dm2 *= 0.5f;
            tm = tl + dm2;
            float q2 = 0.f;
            for (int i = tid; i < D32; i += NT2) {
                float q = fmaxf(fmaf(0.5f, __ldg(xr + i), -tm), 0.f);
                q2 = fmaf(q, q, q2);
            }
            float fm = blockSumAll2(q2, sred) - 1.0f;
            tl = (fm * flb >= 0.f) ? tm : tl;
        }
        tau_m = tm;
        float s3 = 0.f, px = 0.f;
        for (int i = tid; i < D32; i += NT2) {
            float X = 0.5f * __ldg(xr + i);
            float q = fmaxf(X - tau_m, 0.f);
            float p = q * q;
            s3 = fmaf(p, q, s3);
            px = fmaf(p, X, px);
        }
        S3 = blockSumAll2(s3, sred);
        PX = blockSumAll2(px, sred);
    }

    if (tid == 0) {
        int t = load_target(tgt, row, n, D32);
        float xt = __ldg(xr + t);
        // loss = (1-S3)/(alpha*(alpha-1)) + sum(p*input) - input[target]
        //      = (1-S3)/0.75 + 2*PX - xt          (input = 2*X)
        g_rowloss[row] = (1.0f - S3) / 0.75f + 2.0f * PX - xt;
    }
}

// ============ generic fallback (any d) ============
__global__ __launch_bounds__(NT2) void tsallis_gen(const float* __restrict__ in,
                                                   const void* __restrict__ tgt,
                                                   int d, int n) {
    int row = blockIdx.x;
    const float* xr = in + (size_t)row * d;
    __shared__ float sred[NW2];
    float m = -FLT_MAX;
    for (int i = threadIdx.x; i < d; i += NT2) m = fmaxf(m, xr[i]);
    m = warpMax(m);
    __syncthreads();
    if ((threadIdx.x & 31) == 0) sred[threadIdx.x >> 5] = m;
    __syncthreads();
    float bmax = sred[0];
#pragma unroll
    for (int w = 1; w < NW2; w++) bmax = fmaxf(bmax, sred[w]);
    float maxX = 0.5f * bmax;
    float tl = maxX - 1.0f;
    float th0 = maxX - (float)(1.0 / sqrt((double)d));
    float s = 0.f;
    for (int i = threadIdx.x; i < d; i += NT2) {
        float q = fmaxf(fmaf(0.5f, __ldg(xr + i), -tl), 0.f);
        s = fmaf(q, q, s);
    }
    float f_lo = blockSumAll2(s, sred) - 1.0f;
    float dm = th0 - tl, tm = tl;
#pragma unroll 1
    for (int it = 0; it < 15; it++) {
        dm *= 0.5f;
        tm = tl + dm;
        float q2 = 0.f;
        for (int i = threadIdx.x; i < d; i += NT2) {
            float q = fmaxf(fmaf(0.5f, __ldg(xr + i), -tm), 0.f);
            q2 = fmaf(q, q, q2);
        }
        float fm = blockSumAll2(q2, sred) - 1.0f;
        tl = (fm * f_lo >= 0.f) ? tm : tl;
    }
    float s3 = 0.f, px = 0.f;
    for (int i = threadIdx.x; i < d; i += NT2) {
        float X = 0.5f * __ldg(xr + i);
        float q = fmaxf(X - tm, 0.f);
        float p = q * q;
        s3 = fmaf(p, q, s3);
        px = fmaf(p, X, px);
    }
    float S3 = blockSumAll2(s3, sred);
    float PX = blockSumAll2(px, sred);
    if (threadIdx.x == 0) {
        int t = load_target(tgt, row, n, d);
        g_rowloss[row] = (1.0f - S3) / 0.75f + 2.0f * PX - __ldg(xr + t);
    }
}

// ============ mean over rows ============
__global__ __launch_bounds__(1024) void reduce_kernel(float* __restrict__ out, int n) {
    __shared__ float sbuf[32];
    float s = 0.f;
    for (int i = threadIdx.x; i < n; i += 1024) s += g_rowloss[i];
#pragma unroll
    for (int o = 16; o; o >>= 1) s += __shfl_down_sync(0xffffffffu, s, o);
    if ((threadIdx.x & 31) == 0) sbuf[threadIdx.x >> 5] = s;
    __syncthreads();
    if (threadIdx.x < 32) {
        float x = sbuf[threadIdx.x];
#pragma unroll
        for (int o = 16; o; o >>= 1) x += __shfl_down_sync(0xffffffffu, x, o);
        if (threadIdx.x == 0) out[0] = x / (float)n;
    }
}

extern "C" void kernel_launch(void* const* d_in, const int* in_sizes, int n_in,
                              void* d_out, int out_size) {
    int idx_in = 0, idx_tg = 1;
    if (n_in >= 2 && in_sizes[1] > in_sizes[0]) { idx_in = 1; idx_tg = 0; }
    const float* in  = (const float*)d_in[idx_in];
    const void*  tgt = d_in[idx_tg];

    int n = in_sizes[idx_tg];
    if (n <= 0) n = 1;
    int d = in_sizes[idx_in] / n;
    if (n > MAXROWS) n = MAXROWS;

    if (d == D32) {
        filter32k<<<n, NT1>>>(in);
        bisect32k<<<n, NT2>>>(in, tgt, n);
    } else {
        tsallis_gen<<<n, NT2>>>(in, tgt, d, n);
    }
    reduce_kernel<<<1, 1024>>>((float*)d_out, n);
}